// round 1
// baseline (speedup 1.0000x reference)
#include <cuda_runtime.h>

// Problem constants (fixed by the dataset)
#define D_MODEL 1024
#define NHEADS  16
#define DH      64
#define BATCH   4
#define SEQ     2048
#define ROWS    (BATCH * SEQ)     // 8192
#define QKV_N   (3 * D_MODEL)     // 3072

// Scratch: device globals (no allocations allowed anywhere)
__device__ float g_qkv[(size_t)ROWS * QKV_N];   // [row][q(1024) | k(1024) | v(1024)]
__device__ float g_att[(size_t)ROWS * D_MODEL]; // attention output, [B*T, D]

// ---------------------------------------------------------------------------
// Kernel 1: fused QKV projection.  C[m, n] = sum_k x[m,k] * W[n,k] + b[n]
// Treated as one GEMM with N = 3072; each 128-wide n-tile falls entirely in
// one of {Wq, Wk, Wv}.  128x128x16 tiles, 256 threads, 8x8 per thread.
// ---------------------------------------------------------------------------
#define GBM 128
#define GBN 128
#define GBK 16

__global__ __launch_bounds__(256) void qkv_gemm_kernel(
    const float* __restrict__ x,
    const float* __restrict__ Wq, const float* __restrict__ bq,
    const float* __restrict__ Wk, const float* __restrict__ bk,
    const float* __restrict__ Wv, const float* __restrict__ bv)
{
    __shared__ float As[GBK][GBM + 4];
    __shared__ float Bs[GBK][GBN + 4];

    const int n0g = blockIdx.x * GBN;          // global column in [0, 3072)
    const int m0  = blockIdx.y * GBM;
    const int which = n0g >> 10;               // 0:Q 1:K 2:V
    const int n0 = n0g & (D_MODEL - 1);        // column within the weight
    const float* __restrict__ W    = (which == 0) ? Wq : (which == 1 ? Wk : Wv);
    const float* __restrict__ bias = (which == 0) ? bq : (which == 1 ? bk : bv);

    const int tid = threadIdx.x;
    const int tx = tid & 15;                   // output col group
    const int ty = tid >> 4;                   // output row group
    const int lr = tid >> 2;                   // load row (0..63)
    const int lc = (tid & 3) * 4;              // load col chunk (0,4,8,12)

    float acc[8][8];
    #pragma unroll
    for (int i = 0; i < 8; i++)
        #pragma unroll
        for (int j = 0; j < 8; j++) acc[i][j] = 0.0f;

    const float* Aptr = x + (size_t)m0 * D_MODEL;
    const float* Bptr = W + (size_t)n0 * D_MODEL;

    for (int k0 = 0; k0 < D_MODEL; k0 += GBK) {
        float4 a0 = *(const float4*)(Aptr + (size_t)(lr     ) * D_MODEL + k0 + lc);
        float4 a1 = *(const float4*)(Aptr + (size_t)(lr + 64) * D_MODEL + k0 + lc);
        float4 b0 = *(const float4*)(Bptr + (size_t)(lr     ) * D_MODEL + k0 + lc);
        float4 b1 = *(const float4*)(Bptr + (size_t)(lr + 64) * D_MODEL + k0 + lc);
        __syncthreads();   // previous tile's compute must be done before overwrite
        As[lc+0][lr]    = a0.x; As[lc+1][lr]    = a0.y; As[lc+2][lr]    = a0.z; As[lc+3][lr]    = a0.w;
        As[lc+0][lr+64] = a1.x; As[lc+1][lr+64] = a1.y; As[lc+2][lr+64] = a1.z; As[lc+3][lr+64] = a1.w;
        Bs[lc+0][lr]    = b0.x; Bs[lc+1][lr]    = b0.y; Bs[lc+2][lr]    = b0.z; Bs[lc+3][lr]    = b0.w;
        Bs[lc+0][lr+64] = b1.x; Bs[lc+1][lr+64] = b1.y; Bs[lc+2][lr+64] = b1.z; Bs[lc+3][lr+64] = b1.w;
        __syncthreads();

        #pragma unroll
        for (int k = 0; k < GBK; k++) {
            const float4* Ar = (const float4*)&As[k][0];  // row base is 16B aligned (528*k)
            const float4* Br = (const float4*)&Bs[k][0];
            float4 ra0 = Ar[ty*2], ra1 = Ar[ty*2+1];
            float4 rb0 = Br[tx*2], rb1 = Br[tx*2+1];
            float ra[8] = {ra0.x,ra0.y,ra0.z,ra0.w, ra1.x,ra1.y,ra1.z,ra1.w};
            float rb[8] = {rb0.x,rb0.y,rb0.z,rb0.w, rb1.x,rb1.y,rb1.z,rb1.w};
            #pragma unroll
            for (int i = 0; i < 8; i++)
                #pragma unroll
                for (int j = 0; j < 8; j++)
                    acc[i][j] = fmaf(ra[i], rb[j], acc[i][j]);
        }
    }

    float bvals[8];
    #pragma unroll
    for (int j = 0; j < 8; j++) bvals[j] = bias[n0 + tx*8 + j];

    #pragma unroll
    for (int i = 0; i < 8; i++) {
        float* orow = g_qkv + (size_t)(m0 + ty*8 + i) * QKV_N + n0g + tx*8;
        float4 o0 = make_float4(acc[i][0]+bvals[0], acc[i][1]+bvals[1],
                                acc[i][2]+bvals[2], acc[i][3]+bvals[3]);
        float4 o1 = make_float4(acc[i][4]+bvals[4], acc[i][5]+bvals[5],
                                acc[i][6]+bvals[6], acc[i][7]+bvals[7]);
        *(float4*)(orow)     = o0;
        *(float4*)(orow + 4) = o1;
    }
}

// ---------------------------------------------------------------------------
// Kernel 2: causal flash attention. One block = 128 query rows of one (b,h).
// Each thread owns one query row: Q and O accumulators in registers,
// K/V tiles (32 x 64) in smem, per-thread scores staged in smem.
// ---------------------------------------------------------------------------
#define ABN 32

__global__ __launch_bounds__(128) void attn_kernel()
{
    __shared__ float Ks[ABN][DH];
    __shared__ float Vs[ABN][DH];
    __shared__ float Sc[128][ABN + 1];

    const int bh = blockIdx.x;
    const int b  = bh >> 4;
    const int h  = bh & (NHEADS - 1);
    const int mt = (int)gridDim.y - 1 - (int)blockIdx.y;  // heavy tiles launch first
    const int r0 = mt * 128;
    const int tid = threadIdx.x;
    const int t   = r0 + tid;                             // this thread's query row

    const size_t rowbase = (size_t)b * SEQ * QKV_N;
    const float* kbase = g_qkv + rowbase +     D_MODEL + h * DH;
    const float* vbase = g_qkv + rowbase + 2 * D_MODEL + h * DH;

    float q[DH];
    {
        const float* qp = g_qkv + rowbase + (size_t)t * QKV_N + h * DH;
        #pragma unroll
        for (int d4 = 0; d4 < DH/4; d4++) {
            float4 v = *(const float4*)(qp + d4*4);
            q[d4*4+0] = v.x; q[d4*4+1] = v.y; q[d4*4+2] = v.z; q[d4*4+3] = v.w;
        }
    }
    float o[DH];
    #pragma unroll
    for (int d = 0; d < DH; d++) o[d] = 0.0f;

    float mrun = -1e30f;
    float lrun = 0.0f;
    const float scale = 0.125f;                // 1/sqrt(64)
    const int ntiles = mt * (128 / ABN) + (128 / ABN);

    for (int jt = 0; jt < ntiles; jt++) {
        const int j0 = jt * ABN;
        __syncthreads();                       // previous tile's reads complete
        {
            const int key = tid >> 2;          // 0..31
            const int dc  = (tid & 3) * 16;    // 4 threads per key
            const float* kp = kbase + (size_t)(j0 + key) * QKV_N + dc;
            const float* vp = vbase + (size_t)(j0 + key) * QKV_N + dc;
            #pragma unroll
            for (int c = 0; c < 4; c++) {
                *(float4*)&Ks[key][dc + c*4] = *(const float4*)(kp + c*4);
                *(float4*)&Vs[key][dc + c*4] = *(const float4*)(vp + c*4);
            }
        }
        __syncthreads();

        // scores for this thread's row vs 32 keys (broadcast LDS.128 from Ks)
        float mt_tile = -1e30f;
        const float4* K4 = (const float4*)&Ks[0][0];
        #pragma unroll 4
        for (int j = 0; j < ABN; j++) {
            float s = 0.0f;
            #pragma unroll
            for (int d4 = 0; d4 < DH/4; d4++) {
                float4 kk = K4[j*(DH/4) + d4];
                s = fmaf(q[d4*4+0], kk.x, s);
                s = fmaf(q[d4*4+1], kk.y, s);
                s = fmaf(q[d4*4+2], kk.z, s);
                s = fmaf(q[d4*4+3], kk.w, s);
            }
            s *= scale;
            if (j0 + j > t) s = -1e30f;        // causal mask
            Sc[tid][j] = s;
            mt_tile = fmaxf(mt_tile, s);
        }

        // online-softmax rescale + AV accumulation
        const float newm = fmaxf(mrun, mt_tile);
        const float corr = __expf(mrun - newm);
        lrun *= corr;
        #pragma unroll
        for (int d = 0; d < DH; d++) o[d] *= corr;

        const float4* V4 = (const float4*)&Vs[0][0];
        #pragma unroll 2
        for (int j = 0; j < ABN; j++) {
            const float p = __expf(Sc[tid][j] - newm);
            lrun += p;
            #pragma unroll
            for (int d4 = 0; d4 < DH/4; d4++) {
                float4 vv = V4[j*(DH/4) + d4];
                o[d4*4+0] = fmaf(p, vv.x, o[d4*4+0]);
                o[d4*4+1] = fmaf(p, vv.y, o[d4*4+1]);
                o[d4*4+2] = fmaf(p, vv.z, o[d4*4+2]);
                o[d4*4+3] = fmaf(p, vv.w, o[d4*4+3]);
            }
        }
        mrun = newm;
    }

    const float inv_l = 1.0f / lrun;           // l >= 1 always (max element -> p = 1)
    float* op = g_att + ((size_t)b * SEQ + t) * D_MODEL + h * DH;
    #pragma unroll
    for (int d4 = 0; d4 < DH/4; d4++) {
        float4 v = make_float4(o[d4*4+0]*inv_l, o[d4*4+1]*inv_l,
                               o[d4*4+2]*inv_l, o[d4*4+3]*inv_l);
        *(float4*)(op + d4*4) = v;
    }
}

// ---------------------------------------------------------------------------
// Kernel 3: residual add + LayerNorm.  One block per row (8192 rows).
// ---------------------------------------------------------------------------
__global__ __launch_bounds__(256) void add_ln_kernel(
    const float* __restrict__ x, const float* __restrict__ gamma,
    const float* __restrict__ beta, float* __restrict__ out)
{
    __shared__ float red[8];
    __shared__ float s_mu, s_rstd;
    const int row  = blockIdx.x;
    const int tid  = threadIdx.x;
    const int lane = tid & 31;
    const int wid  = tid >> 5;

    float4 xv = *(const float4*)(x     + (size_t)row * D_MODEL + tid*4);
    float4 av = *(const float4*)(g_att + (size_t)row * D_MODEL + tid*4);
    float4 y  = make_float4(xv.x+av.x, xv.y+av.y, xv.z+av.z, xv.w+av.w);

    float s = y.x + y.y + y.z + y.w;
    #pragma unroll
    for (int off = 16; off; off >>= 1) s += __shfl_xor_sync(0xffffffffu, s, off);
    if (lane == 0) red[wid] = s;
    __syncthreads();
    if (tid == 0) {
        float tot = 0.0f;
        #pragma unroll
        for (int i = 0; i < 8; i++) tot += red[i];
        s_mu = tot * (1.0f / D_MODEL);
    }
    __syncthreads();
    const float mu = s_mu;

    const float dx0 = y.x - mu, dx1 = y.y - mu, dx2 = y.z - mu, dx3 = y.w - mu;
    float v = dx0*dx0 + dx1*dx1 + dx2*dx2 + dx3*dx3;
    #pragma unroll
    for (int off = 16; off; off >>= 1) v += __shfl_xor_sync(0xffffffffu, v, off);
    if (lane == 0) red[wid] = v;
    __syncthreads();
    if (tid == 0) {
        float tot = 0.0f;
        #pragma unroll
        for (int i = 0; i < 8; i++) tot += red[i];
        s_rstd = rsqrtf(tot * (1.0f / D_MODEL) + 1e-5f);
    }
    __syncthreads();
    const float r = s_rstd;

    float4 g  = *(const float4*)(gamma + tid*4);
    float4 be = *(const float4*)(beta  + tid*4);
    float4 ov = make_float4(dx0*r*g.x + be.x, dx1*r*g.y + be.y,
                            dx2*r*g.z + be.z, dx3*r*g.w + be.w);
    *(float4*)(out + (size_t)row * D_MODEL + tid*4) = ov;
}

// ---------------------------------------------------------------------------
// Entry point (graph-capturable: kernel launches only)
// ---------------------------------------------------------------------------
extern "C" void kernel_launch(void* const* d_in, const int* in_sizes, int n_in,
                              void* d_out, int out_size)
{
    const float* x     = (const float*)d_in[0];
    const float* Wq    = (const float*)d_in[1];
    const float* bq    = (const float*)d_in[2];
    const float* Wk    = (const float*)d_in[3];
    const float* bk    = (const float*)d_in[4];
    const float* Wv    = (const float*)d_in[5];
    const float* bv    = (const float*)d_in[6];
    const float* gamma = (const float*)d_in[7];
    const float* beta  = (const float*)d_in[8];
    float* out = (float*)d_out;

    qkv_gemm_kernel<<<dim3(QKV_N / GBN, ROWS / GBM), 256>>>(x, Wq, bq, Wk, bk, Wv, bv);
    attn_kernel<<<dim3(BATCH * NHEADS, SEQ / 128), 128>>>();
    add_ln_kernel<<<ROWS, 256>>>(x, gamma, beta, out);
}

// round 11
// speedup vs baseline: 5.6513x; 5.6513x over previous
#include <cuda_runtime.h>
#include <cstdint>

// Problem constants (fixed by the dataset)
#define D_MODEL 1024
#define NHEADS  16
#define DH      64
#define BATCH   4
#define SEQ     2048
#define ROWS    (BATCH * SEQ)     // 8192
#define QKV_N   (3 * D_MODEL)     // 3072

// Scratch: device globals (no allocations allowed anywhere)
__device__ float g_qkv[(size_t)ROWS * QKV_N];   // [row][q(1024) | k(1024) | v(1024)]
__device__ float g_att[(size_t)ROWS * D_MODEL]; // attention output, [B*T, D]

// ---------------------------------------------------------------------------
// Shared tf32 mma.sync machinery (m16n8k8, row.col, fp32 accum).
// Fragment conventions (lane = 4*g + tg, g in 0..7, tg in 0..3):
//   A (m16k8): a0=(g,tg) a1=(g+8,tg) a2=(g,tg+4) a3=(g+8,tg+4)
//   B (n8k8):  b0=(g,tg) b1=(g,tg+4)
//   C (m16n8): c0=(g,2tg) c1=(g,2tg+1) c2=(g+8,2tg) c3=(g+8,2tg+1)
// ---------------------------------------------------------------------------
__device__ __forceinline__ float to_tf32(float x) {
    float r;
    asm("cvt.rna.tf32.f32 %0, %1;" : "=f"(r) : "f"(x));
    return r;
}

__device__ __forceinline__ void mma_tf32(float c[4],
                                         const uint32_t a[4],
                                         const uint32_t b[2]) {
    asm volatile(
        "mma.sync.aligned.m16n8k8.row.col.f32.tf32.tf32.f32 "
        "{%0,%1,%2,%3}, {%4,%5,%6,%7}, {%8,%9}, {%0,%1,%2,%3};\n"
        : "+f"(c[0]), "+f"(c[1]), "+f"(c[2]), "+f"(c[3])
        : "r"(a[0]), "r"(a[1]), "r"(a[2]), "r"(a[3]),
          "r"(b[0]), "r"(b[1]));
}

// ---------------------------------------------------------------------------
// Kernel 1: fused QKV projection on tensor cores (tf32 mma.sync, fp32 accum).
// Block tile 128x128xK32, 8 warps in 2x4, warp tile 64x32.
// Smem row stride 36 floats (== 4 mod 32) -> conflict-free fragment LDS.
// ---------------------------------------------------------------------------
#define BM 128
#define BN 128
#define BK 32
#define SSTR 36
#define NKT (D_MODEL / BK)   // 32 k-tiles

__global__ __launch_bounds__(256) void qkv_gemm_tf32_kernel(
    const float* __restrict__ x,
    const float* __restrict__ Wq, const float* __restrict__ bq,
    const float* __restrict__ Wk, const float* __restrict__ bk,
    const float* __restrict__ Wv, const float* __restrict__ bv)
{
    __shared__ float As[BM * SSTR];
    __shared__ float Bs[BN * SSTR];

    const int n0g = blockIdx.x * BN;           // global column in [0, 3072)
    const int m0  = blockIdx.y * BM;
    const int which = n0g >> 10;               // 0:Q 1:K 2:V
    const int n0 = n0g & (D_MODEL - 1);
    const float* __restrict__ W    = (which == 0) ? Wq : (which == 1 ? Wk : Wv);
    const float* __restrict__ bias = (which == 0) ? bq : (which == 1 ? bk : bv);

    const int tid    = threadIdx.x;
    const int warp   = tid >> 5;
    const int lane   = tid & 31;
    const int warp_m = warp >> 2;              // 0..1
    const int warp_n = warp & 3;               // 0..3
    const int g      = lane >> 2;              // group id 0..7
    const int tg     = lane & 3;               // thread-in-group 0..3

    const int lrow = tid >> 3;                 // 0..31 (base row)
    const int lcol = (tid & 7) * 4;            // 0,4,...,28

    float4 pa[4], pb[4];
    const float* Aptr = x + (size_t)m0 * D_MODEL;
    const float* Bptr = W + (size_t)n0 * D_MODEL;

    float c[4][4][4];
    #pragma unroll
    for (int mf = 0; mf < 4; mf++)
        #pragma unroll
        for (int nf = 0; nf < 4; nf++)
            #pragma unroll
            for (int e = 0; e < 4; e++) c[mf][nf][e] = 0.0f;

    #pragma unroll
    for (int t = 0; t < 4; t++) {
        pa[t] = *(const float4*)(Aptr + (size_t)(lrow + 32*t) * D_MODEL + lcol);
        pb[t] = *(const float4*)(Bptr + (size_t)(lrow + 32*t) * D_MODEL + lcol);
    }

    const uint32_t* A32 = (const uint32_t*)As;
    const uint32_t* B32 = (const uint32_t*)Bs;

    for (int kt = 0; kt < NKT; kt++) {
        __syncthreads();
        #pragma unroll
        for (int t = 0; t < 4; t++) {
            float4 av = make_float4(to_tf32(pa[t].x), to_tf32(pa[t].y),
                                    to_tf32(pa[t].z), to_tf32(pa[t].w));
            float4 bv = make_float4(to_tf32(pb[t].x), to_tf32(pb[t].y),
                                    to_tf32(pb[t].z), to_tf32(pb[t].w));
            *(float4*)&As[(lrow + 32*t) * SSTR + lcol] = av;
            *(float4*)&Bs[(lrow + 32*t) * SSTR + lcol] = bv;
        }
        __syncthreads();

        if (kt + 1 < NKT) {
            const int k0 = (kt + 1) * BK;
            #pragma unroll
            for (int t = 0; t < 4; t++) {
                pa[t] = *(const float4*)(Aptr + (size_t)(lrow + 32*t) * D_MODEL + k0 + lcol);
                pb[t] = *(const float4*)(Bptr + (size_t)(lrow + 32*t) * D_MODEL + k0 + lcol);
            }
        }

        #pragma unroll
        for (int kk = 0; kk < BK; kk += 8) {
            uint32_t a[4][4], b[4][2];
            #pragma unroll
            for (int mf = 0; mf < 4; mf++) {
                const int m = warp_m * 64 + mf * 16;
                a[mf][0] = A32[(m + g)     * SSTR + kk + tg];
                a[mf][1] = A32[(m + g + 8) * SSTR + kk + tg];
                a[mf][2] = A32[(m + g)     * SSTR + kk + tg + 4];
                a[mf][3] = A32[(m + g + 8) * SSTR + kk + tg + 4];
            }
            #pragma unroll
            for (int nf = 0; nf < 4; nf++) {
                const int n = warp_n * 32 + nf * 8;
                b[nf][0] = B32[(n + g) * SSTR + kk + tg];
                b[nf][1] = B32[(n + g) * SSTR + kk + tg + 4];
            }
            #pragma unroll
            for (int mf = 0; mf < 4; mf++)
                #pragma unroll
                for (int nf = 0; nf < 4; nf++)
                    mma_tf32(c[mf][nf], a[mf], b[nf]);
        }
    }

    #pragma unroll
    for (int mf = 0; mf < 4; mf++) {
        const int gr = m0 + warp_m * 64 + mf * 16 + g;
        #pragma unroll
        for (int nf = 0; nf < 4; nf++) {
            const int gc = n0g + warp_n * 32 + nf * 8 + tg * 2;
            const float b0v = bias[(gc & (D_MODEL - 1))];
            const float b1v = bias[(gc & (D_MODEL - 1)) + 1];
            float2 v0 = make_float2(c[mf][nf][0] + b0v, c[mf][nf][1] + b1v);
            float2 v1 = make_float2(c[mf][nf][2] + b0v, c[mf][nf][3] + b1v);
            *(float2*)(g_qkv + (size_t)gr       * QKV_N + gc) = v0;
            *(float2*)(g_qkv + (size_t)(gr + 8) * QKV_N + gc) = v1;
        }
    }
}

// ---------------------------------------------------------------------------
// Kernel 2: causal flash attention on tensor cores (FA2 style).
// Block = 128 query rows of one (b,h); 256 threads = 8 warps, warp w owns
// rows 16w..16w+15. Per key-tile of 32:
//   QK^T mma (Q frags register-resident) -> scores to smem (scale+mask)
//   128 row-threads: online softmax on their row, p back to smem as tf32
//   all warps: rescale O frags by corr, P*V mma accumulate into O frags.
// ---------------------------------------------------------------------------
#define ATN  32     // keys per tile
#define QSTR 68     // Ks row stride (64 dims + pad), 68 % 32 == 4
#define PSTR 36     // Ps / Vt row stride (32 cols + pad), 36 % 32 == 4

__global__ __launch_bounds__(256) void attn_mma_kernel()
{
    __shared__ float Ks[ATN * QSTR];      // [key][dim]  32x64 (tf32)
    __shared__ float Vt[DH * PSTR];       // [dim][key]  64x32 (tf32)
    __shared__ float Ps[128 * PSTR];      // [row][key] 128x32 scores -> p
    __shared__ float Corr[128];
    __shared__ float Lrow[128];

    const int bh = blockIdx.x;
    const int b  = bh >> 4;
    const int h  = bh & (NHEADS - 1);
    const int mt = (int)gridDim.y - 1 - (int)blockIdx.y;  // heavy tiles first
    const int r0 = mt * 128;
    const int tid  = threadIdx.x;
    const int warp = tid >> 5;
    const int lane = tid & 31;
    const int g  = lane >> 2;
    const int tg = lane & 3;
    const int m  = warp * 16;             // warp's row offset within block

    const size_t rowbase = (size_t)b * SEQ * QKV_N;
    const float* kgbase = g_qkv + rowbase +     D_MODEL + h * DH;
    const float* vgbase = g_qkv + rowbase + 2 * D_MODEL + h * DH;

    // Q fragments, register-resident for the whole kernel (tf32)
    uint32_t qa[8][4];
    {
        const float* qp = g_qkv + rowbase + (size_t)(r0 + m) * QKV_N + h * DH;
        #pragma unroll
        for (int ks = 0; ks < 8; ks++) {
            const int k = ks * 8;
            qa[ks][0] = __float_as_uint(to_tf32(qp[(size_t)(g    ) * QKV_N + k + tg    ]));
            qa[ks][1] = __float_as_uint(to_tf32(qp[(size_t)(g + 8) * QKV_N + k + tg    ]));
            qa[ks][2] = __float_as_uint(to_tf32(qp[(size_t)(g    ) * QKV_N + k + tg + 4]));
            qa[ks][3] = __float_as_uint(to_tf32(qp[(size_t)(g + 8) * QKV_N + k + tg + 4]));
        }
    }

    float o[8][4];                        // O accumulator frags: 8 n-frags of 8 dims
    #pragma unroll
    for (int nf = 0; nf < 8; nf++)
        #pragma unroll
        for (int e = 0; e < 4; e++) o[nf][e] = 0.0f;

    // per-row softmax state (row threads tid < 128, row = tid)
    float mrun = -1e30f;
    float lrun = 0.0f;

    const int ntiles = (mt + 1) * (128 / ATN);

    for (int jt = 0; jt < ntiles; jt++) {
        const int j0 = jt * ATN;
        __syncthreads();                  // prior tile's Ps/Vt reads complete

        // load K tile (32x64) and V tile transposed (64x32), tf32-converted
        {
            int idx = tid;
            #pragma unroll
            for (int it = 0; it < 2; it++, idx += 256) {
                const int key = idx >> 4;          // 16 float4 per key row
                const int dc  = (idx & 15) * 4;
                float4 kv = *(const float4*)(kgbase + (size_t)(j0 + key) * QKV_N + dc);
                *(float4*)&Ks[key * QSTR + dc] =
                    make_float4(to_tf32(kv.x), to_tf32(kv.y), to_tf32(kv.z), to_tf32(kv.w));
            }
            idx = tid;
            #pragma unroll
            for (int it = 0; it < 2; it++, idx += 256) {
                const int key = idx >> 4;
                const int dc  = (idx & 15) * 4;
                float4 vv = *(const float4*)(vgbase + (size_t)(j0 + key) * QKV_N + dc);
                Vt[(dc + 0) * PSTR + key] = to_tf32(vv.x);
                Vt[(dc + 1) * PSTR + key] = to_tf32(vv.y);
                Vt[(dc + 2) * PSTR + key] = to_tf32(vv.z);
                Vt[(dc + 3) * PSTR + key] = to_tf32(vv.w);
            }
        }
        __syncthreads();

        // QK^T: 16 rows x 32 keys, K=64
        float c[4][4];
        #pragma unroll
        for (int nf = 0; nf < 4; nf++)
            #pragma unroll
            for (int e = 0; e < 4; e++) c[nf][e] = 0.0f;

        const uint32_t* K32 = (const uint32_t*)Ks;
        #pragma unroll
        for (int ks = 0; ks < 8; ks++) {
            #pragma unroll
            for (int nf = 0; nf < 4; nf++) {
                uint32_t bb[2];
                bb[0] = K32[(nf * 8 + g) * QSTR + ks * 8 + tg];
                bb[1] = K32[(nf * 8 + g) * QSTR + ks * 8 + tg + 4];
                mma_tf32(c[nf], qa[ks], bb);
            }
        }

        // scores -> Ps with scale + causal mask
        {
            const int rowa = r0 + m + g;
            const int rowb = rowa + 8;
            #pragma unroll
            for (int nf = 0; nf < 4; nf++) {
                const int col0 = j0 + nf * 8 + 2 * tg;
                const int col1 = col0 + 1;
                Ps[(m + g)     * PSTR + nf * 8 + 2 * tg]     = (col0 > rowa) ? -1e30f : c[nf][0] * 0.125f;
                Ps[(m + g)     * PSTR + nf * 8 + 2 * tg + 1] = (col1 > rowa) ? -1e30f : c[nf][1] * 0.125f;
                Ps[(m + g + 8) * PSTR + nf * 8 + 2 * tg]     = (col0 > rowb) ? -1e30f : c[nf][2] * 0.125f;
                Ps[(m + g + 8) * PSTR + nf * 8 + 2 * tg + 1] = (col1 > rowb) ? -1e30f : c[nf][3] * 0.125f;
            }
        }
        __syncthreads();

        // online softmax: one thread per row
        if (tid < 128) {
            float* pr = &Ps[tid * PSTR];
            float mx = mrun;
            #pragma unroll
            for (int j = 0; j < ATN; j++) mx = fmaxf(mx, pr[j]);
            const float corr = __expf(mrun - mx);
            float s = 0.0f;
            #pragma unroll
            for (int j = 0; j < ATN; j++) {
                const float p = __expf(pr[j] - mx);
                s += p;
                pr[j] = to_tf32(p);
            }
            lrun = lrun * corr + s;
            mrun = mx;
            Corr[tid] = corr;
        }
        __syncthreads();

        // rescale O frags, then P*V accumulate
        {
            const float cg  = Corr[m + g];
            const float cg8 = Corr[m + g + 8];
            #pragma unroll
            for (int nf = 0; nf < 8; nf++) {
                o[nf][0] *= cg;  o[nf][1] *= cg;
                o[nf][2] *= cg8; o[nf][3] *= cg8;
            }
        }
        const uint32_t* P32 = (const uint32_t*)Ps;
        const uint32_t* V32 = (const uint32_t*)Vt;
        #pragma unroll
        for (int ks = 0; ks < 4; ks++) {          // K = 32 keys
            uint32_t pa[4];
            pa[0] = P32[(m + g)     * PSTR + ks * 8 + tg];
            pa[1] = P32[(m + g + 8) * PSTR + ks * 8 + tg];
            pa[2] = P32[(m + g)     * PSTR + ks * 8 + tg + 4];
            pa[3] = P32[(m + g + 8) * PSTR + ks * 8 + tg + 4];
            #pragma unroll
            for (int nf = 0; nf < 8; nf++) {      // N = 64 dims
                uint32_t bb[2];
                bb[0] = V32[(nf * 8 + g) * PSTR + ks * 8 + tg];
                bb[1] = V32[(nf * 8 + g) * PSTR + ks * 8 + tg + 4];
                mma_tf32(o[nf], pa, bb);
            }
        }
    }

    if (tid < 128) Lrow[tid] = 1.0f / lrun;       // l >= 1 always
    __syncthreads();

    {
        const float li0 = Lrow[m + g];
        const float li1 = Lrow[m + g + 8];
        float* ob = g_att + ((size_t)b * SEQ + r0 + m) * D_MODEL + h * DH;
        #pragma unroll
        for (int nf = 0; nf < 8; nf++) {
            const int col = nf * 8 + 2 * tg;
            *(float2*)(ob + (size_t)(g    ) * D_MODEL + col) =
                make_float2(o[nf][0] * li0, o[nf][1] * li0);
            *(float2*)(ob + (size_t)(g + 8) * D_MODEL + col) =
                make_float2(o[nf][2] * li1, o[nf][3] * li1);
        }
    }
}

// ---------------------------------------------------------------------------
// Kernel 3: residual add + LayerNorm (unchanged from passing R1 kernel).
// ---------------------------------------------------------------------------
__global__ __launch_bounds__(256) void add_ln_kernel(
    const float* __restrict__ x, const float* __restrict__ gamma,
    const float* __restrict__ beta, float* __restrict__ out)
{
    __shared__ float red[8];
    __shared__ float s_mu, s_rstd;
    const int row  = blockIdx.x;
    const int tid  = threadIdx.x;
    const int lane = tid & 31;
    const int wid  = tid >> 5;

    float4 xv = *(const float4*)(x     + (size_t)row * D_MODEL + tid*4);
    float4 av = *(const float4*)(g_att + (size_t)row * D_MODEL + tid*4);
    float4 y  = make_float4(xv.x+av.x, xv.y+av.y, xv.z+av.z, xv.w+av.w);

    float s = y.x + y.y + y.z + y.w;
    #pragma unroll
    for (int off = 16; off; off >>= 1) s += __shfl_xor_sync(0xffffffffu, s, off);
    if (lane == 0) red[wid] = s;
    __syncthreads();
    if (tid == 0) {
        float tot = 0.0f;
        #pragma unroll
        for (int i = 0; i < 8; i++) tot += red[i];
        s_mu = tot * (1.0f / D_MODEL);
    }
    __syncthreads();
    const float mu = s_mu;

    const float dx0 = y.x - mu, dx1 = y.y - mu, dx2 = y.z - mu, dx3 = y.w - mu;
    float v = dx0*dx0 + dx1*dx1 + dx2*dx2 + dx3*dx3;
    #pragma unroll
    for (int off = 16; off; off >>= 1) v += __shfl_xor_sync(0xffffffffu, v, off);
    if (lane == 0) red[wid] = v;
    __syncthreads();
    if (tid == 0) {
        float tot = 0.0f;
        #pragma unroll
        for (int i = 0; i < 8; i++) tot += red[i];
        s_rstd = rsqrtf(tot * (1.0f / D_MODEL) + 1e-5f);
    }
    __syncthreads();
    const float r = s_rstd;

    float4 gm = *(const float4*)(gamma + tid*4);
    float4 be = *(const float4*)(beta  + tid*4);
    float4 ov = make_float4(dx0*r*gm.x + be.x, dx1*r*gm.y + be.y,
                            dx2*r*gm.z + be.z, dx3*r*gm.w + be.w);
    *(float4*)(out + (size_t)row * D_MODEL + tid*4) = ov;
}

// ---------------------------------------------------------------------------
// Entry point (graph-capturable: kernel launches only)
// ---------------------------------------------------------------------------
extern "C" void kernel_launch(void* const* d_in, const int* in_sizes, int n_in,
                              void* d_out, int out_size)
{
    const float* x     = (const float*)d_in[0];
    const float* Wq    = (const float*)d_in[1];
    const float* bq    = (const float*)d_in[2];
    const float* Wk    = (const float*)d_in[3];
    const float* bk    = (const float*)d_in[4];
    const float* Wv    = (const float*)d_in[5];
    const float* bv    = (const float*)d_in[6];
    const float* gamma = (const float*)d_in[7];
    const float* beta  = (const float*)d_in[8];
    float* out = (float*)d_out;

    qkv_gemm_tf32_kernel<<<dim3(QKV_N / BN, ROWS / BM), 256>>>(x, Wq, bq, Wk, bk, Wv, bv);
    attn_mma_kernel<<<dim3(BATCH * NHEADS, SEQ / 128), 256>>>();
    add_ln_kernel<<<ROWS, 256>>>(x, gamma, beta, out);
}